// round 4
// baseline (speedup 1.0000x reference)
#include <cuda_runtime.h>
#include <math.h>

#define NB 32
#define NA 5
#define NC 20
#define NH 64
#define NW 64
#define NT 50
#define HW (NH*NW)                  // 4096
#define CELLS_PER_B (NA*HW)         // 20480
#define NCELL (NB*CELLS_PER_B)      // 655360
#define NCH (5+NC)                  // 25
#define TPB 256
#define CPT 4                       // cells per thread
#define NBLK (NCELL/(TPB*CPT))      // 640

// Compacted per-target records (device globals — no allocation allowed)
__device__ int    g_cnt[NB];
__device__ int    g_cell[NB*NT];
__device__ float4 g_box[NB*NT];    // (gl, gt, gr, gb)
__device__ float  g_thr[NB*NT];    // 0.375 * gw*gh
__device__ float  g_ga[NB*NT];
__device__ float  g_tx[NB*NT], g_ty[NB*NT], g_twv[NB*NT], g_thv[NB*NT];
__device__ int    g_tcls[NB*NT];
__device__ float  g_part[NBLK];
__device__ double g_fix;
__device__ int    g_ticket = 0;

__global__ void k_prep(const float* __restrict__ target,
                       const float* __restrict__ anchors) {
    __shared__ int s_slot[NT];
    int b = blockIdx.x;
    int t = threadIdx.x;
    if (b == 0 && t == 0) g_fix = 0.0;

    float gx=0, gy=0, gw=0, gh=0, cls=0;
    bool v = false;
    if (t < NT) {
        const float* tg = target + (size_t)(b*NT + t)*5;
        cls = tg[0];
        float xn = tg[1], yn = tg[2], wn = tg[3], hn = tg[4];
        v = (xn > 0.0f);
        gx = xn * (float)NW; gy = yn * (float)NH;
        gw = wn * (float)NW; gh = hn * (float)NH;
        s_slot[t] = v ? 1 : 0;
    }
    __syncthreads();
    if (t == 0) {
        int c = 0;
        #pragma unroll
        for (int i = 0; i < NT; i++) { int f = s_slot[i]; s_slot[i] = c; c += f; }
        g_cnt[b] = c;
    }
    __syncthreads();

    if (v) {
        int best = 0; float bi = -1.0f, baw = anchors[0], bah = anchors[1];
        #pragma unroll
        for (int a = 0; a < NA; a++) {
            float aw = anchors[2*a], ah = anchors[2*a+1];
            float inter = fminf(gw, aw) * fminf(gh, ah);
            float uni = fmaxf(gw*gh + aw*ah - inter, 1e-10f);
            float iou = inter / uni;
            if (iou > bi) { bi = iou; best = a; baw = aw; bah = ah; }
        }
        int gi = min(max((int)floorf(gx), 0), NW-1);
        int gj = min(max((int)floorf(gy), 0), NH-1);
        int s = b*NT + s_slot[t];
        g_cell[s] = ((b*NA + best)*NH + gj)*NW + gi;
        g_box[s]  = make_float4(gx - 0.5f*gw, gy - 0.5f*gh,
                                gx + 0.5f*gw, gy + 0.5f*gh);
        float area = gw * gh;
        g_ga[s]  = area;
        g_thr[s] = 0.375f * area;
        g_tx[s]  = gx - (float)gi;
        g_ty[s]  = gy - (float)gj;
        g_twv[s] = logf(fmaxf(gw, 1e-10f) / baw);
        g_thv[s] = logf(fmaxf(gh, 1e-10f) / bah);
        g_tcls[s] = (int)cls;
    }
}

__device__ __forceinline__ float fast_sigmoid(float v) {
    return __fdividef(1.0f, 1.0f + __expf(-v));
}

// Rare-path kernel: for each matched cell (~12/batch), replace the default
// (unmatched) contribution with the true one. ~384 active threads total.
__global__ void k_fix(const float* __restrict__ out,
                      const float* __restrict__ anchors) {
    int b = blockIdx.x;
    int t = threadIdx.x;
    int cnt = g_cnt[b];
    if (t >= cnt) return;
    int s = b*NT + t;
    int cell = g_cell[s];
    // last-writer-wins: only the last target mapping to this cell applies
    for (int u = t + 1; u < cnt; u++)
        if (g_cell[b*NT + u] == cell) return;

    int within = cell - b*CELLS_PER_B;
    int a = within >> 12;
    int ji = within & 4095;
    int i = ji & 63, j = ji >> 6;
    int base = (b*(NA*NCH) + a*NCH)*HW + ji;
    float o0 = out[base];
    float o1 = out[base +   HW];
    float o2 = out[base + 2*HW];
    float o3 = out[base + 3*HW];
    float o4 = out[base + 4*HW];

    float aw = anchors[2*a], ah = anchors[2*a+1];
    float x    = fast_sigmoid(o0);
    float y    = fast_sigmoid(o1);
    float conf = fast_sigmoid(o4);
    float pw = __expf(o2) * aw;
    float ph = __expf(o3) * ah;
    float px = x + (float)i, py = y + (float)j;
    float pl = px - 0.5f*pw, pr = px + 0.5f*pw;
    float pt = py - 0.5f*ph, pb = py + 0.5f*ph;
    float parea = pw * ph;
    float pthr  = 0.375f * parea;

    // sil for this cell (must mirror k_main's formula)
    bool sil = false;
    for (int u = 0; u < cnt; u++) {
        float4 g = g_box[b*NT + u];
        float l  = fmaxf(pl, g.x);
        float tt = fmaxf(pt, g.y);
        float r  = fminf(pr, g.z);
        float bb = fminf(pb, g.w);
        float inter = fmaxf(r - l, 0.0f) * fmaxf(bb - tt, 0.0f);
        sil = sil | (inter > pthr + g_thr[b*NT + u]);
    }

    // default contribution computed by k_main for this cell
    float ddx = x - 0.5f, ddy = y - 0.5f;
    float D = 0.5f*(ddx*ddx + ddy*ddy + o2*o2 + o3*o3)
            + (sil ? 0.0f : 0.5f*conf*conf);

    // true contribution
    float4 g = g_box[s];
    float ga = g_ga[s];
    float l  = fmaxf(pl, g.x);
    float tt = fmaxf(pt, g.y);
    float rr = fminf(pr, g.z);
    float bb = fminf(pb, g.w);
    float inter = fmaxf(rr - l, 0.0f) * fmaxf(bb - tt, 0.0f);
    float uni = fmaxf(parea + ga - inter, 1e-10f);
    float tconf = __fdividef(inter, uni);

    int tcls = g_tcls[s];
    int cbase = base + 5*HW;
    float m = -1e30f;
    float lg[NC];
    #pragma unroll
    for (int q = 0; q < NC; q++) {
        lg[q] = out[cbase + q*HW];
        m = fmaxf(m, lg[q]);
    }
    float sum = 0.0f;
    #pragma unroll
    for (int q = 0; q < NC; q++) sum += __expf(lg[q] - m);
    float lcls = m + logf(sum) - lg[tcls];

    float dx = x - g_tx[s], dy = y - g_ty[s];
    float dw = o2 - g_twv[s], dh = o3 - g_thv[s];
    float dc = conf - tconf;
    float T = 0.5f*(dx*dx + dy*dy + dw*dw + dh*dh + 5.0f*(dc*dc)) + lcls;

    atomicAdd(&g_fix, (double)(T - D));
}

// Hot kernel: 4 cells/thread, every cell treated as unmatched.
__global__ void __launch_bounds__(TPB, 6) k_main(const float* __restrict__ out,
                                                 const float* __restrict__ anchors,
                                                 float* __restrict__ res) {
    __shared__ int    s_cnt;
    __shared__ float4 s_box[NT];
    __shared__ float  s_thr[NT];
    __shared__ float  s_ws[TPB/32];
    __shared__ bool   s_last;

    int tid = threadIdx.x;
    int gid0 = (blockIdx.x * TPB + tid) * CPT;
    int b = gid0 / CELLS_PER_B;
    int within = gid0 - b * CELLS_PER_B;
    int a = within >> 12;
    int ji = within & 4095;
    int j = ji >> 6, i0 = ji & 63;

    if (tid == 0) s_cnt = g_cnt[b];
    __syncthreads();
    int cnt = s_cnt;
    if (tid < cnt) {
        int r = b*NT + tid;
        s_box[tid] = g_box[r];
        s_thr[tid] = g_thr[r];
    }
    __syncthreads();

    int base = (b*(NA*NCH) + a*NCH)*HW + ji;
    float4 v0 = *(const float4*)(out + base);
    float4 v1 = *(const float4*)(out + base +   HW);
    float4 v2 = *(const float4*)(out + base + 2*HW);
    float4 v3 = *(const float4*)(out + base + 3*HW);
    float4 v4 = *(const float4*)(out + base + 4*HW);

    float o2a[CPT] = {v2.x, v2.y, v2.z, v2.w};
    float o3a[CPT] = {v3.x, v3.y, v3.z, v3.w};
    float xs[CPT]  = {fast_sigmoid(v0.x), fast_sigmoid(v0.y), fast_sigmoid(v0.z), fast_sigmoid(v0.w)};
    float ys[CPT]  = {fast_sigmoid(v1.x), fast_sigmoid(v1.y), fast_sigmoid(v1.z), fast_sigmoid(v1.w)};
    float cf[CPT]  = {fast_sigmoid(v4.x), fast_sigmoid(v4.y), fast_sigmoid(v4.z), fast_sigmoid(v4.w)};

    float aw = anchors[2*a], ah = anchors[2*a+1];
    float pl[CPT], pr[CPT], pt[CPT], pb[CPT], pthr[CPT], confsq[CPT];
    float acc = 0.0f;
    #pragma unroll
    for (int c = 0; c < CPT; c++) {
        float pw = __expf(o2a[c]) * aw;
        float ph = __expf(o3a[c]) * ah;
        float px = xs[c] + (float)(i0 + c);
        float py = ys[c] + (float)j;
        pl[c] = px - 0.5f*pw;  pr[c] = px + 0.5f*pw;
        pt[c] = py - 0.5f*ph;  pb[c] = py + 0.5f*ph;
        pthr[c] = 0.375f * (pw * ph);
        confsq[c] = 0.5f * cf[c] * cf[c];
        float dx = xs[c] - 0.5f, dy = ys[c] - 0.5f;
        acc += 0.5f*(dx*dx + dy*dy + o2a[c]*o2a[c] + o3a[c]*o3a[c]);
    }

    bool sil[CPT] = {false, false, false, false};
    #pragma unroll 1
    for (int t = 0; t < cnt; t++) {
        float4 g = s_box[t];
        float thr = s_thr[t];
        #pragma unroll
        for (int c = 0; c < CPT; c++) {
            float l  = fmaxf(pl[c], g.x);
            float tt = fmaxf(pt[c], g.y);
            float r  = fminf(pr[c], g.z);
            float bb = fminf(pb[c], g.w);
            float inter = fmaxf(r - l, 0.0f) * fmaxf(bb - tt, 0.0f);
            sil[c] = sil[c] | (inter > pthr[c] + thr);
        }
    }
    #pragma unroll
    for (int c = 0; c < CPT; c++)
        acc += sil[c] ? 0.0f : confsq[c];

    // block reduction (fp32) -> one partial per block
    float v = acc;
    #pragma unroll
    for (int o = 16; o > 0; o >>= 1)
        v += __shfl_down_sync(0xffffffffu, v, o);
    int lane = tid & 31, w = tid >> 5;
    if (lane == 0) s_ws[w] = v;
    __syncthreads();
    if (w == 0) {
        v = (lane < TPB/32) ? s_ws[lane] : 0.0f;
        #pragma unroll
        for (int o = 4; o > 0; o >>= 1)
            v += __shfl_down_sync(0xffffffffu, v, o);
        if (lane == 0) g_part[blockIdx.x] = v;
    }

    // arrival ticket: last block sums the 640 partials (+ fix) in double
    __threadfence();
    __syncthreads();
    if (tid == 0) {
        int old = atomicAdd(&g_ticket, 1);
        s_last = (old == NBLK - 1);
    }
    __syncthreads();
    if (s_last) {
        double dacc = 0.0;
        for (int idx = tid; idx < NBLK; idx += TPB) dacc += (double)g_part[idx];
        #pragma unroll
        for (int o = 16; o > 0; o >>= 1)
            dacc += __shfl_down_sync(0xffffffffu, dacc, o);
        __shared__ double s_dw[TPB/32];
        if (lane == 0) s_dw[w] = dacc;
        __syncthreads();
        if (w == 0) {
            dacc = (lane < TPB/32) ? s_dw[lane] : 0.0;
            #pragma unroll
            for (int o = 4; o > 0; o >>= 1)
                dacc += __shfl_down_sync(0xffffffffu, dacc, o);
            if (lane == 0) { res[0] = (float)(dacc + g_fix); g_ticket = 0; }
        }
    }
}

extern "C" void kernel_launch(void* const* d_in, const int* in_sizes, int n_in,
                              void* d_out, int out_size) {
    const float* output  = (const float*)d_in[0];
    const float* target  = (const float*)d_in[1];
    const float* anchors = (const float*)d_in[2];
    float* res = (float*)d_out;
    (void)in_sizes; (void)n_in; (void)out_size;

    k_prep<<<NB, 64>>>(target, anchors);
    k_fix<<<NB, 64>>>(output, anchors);
    k_main<<<NBLK, TPB>>>(output, anchors, res);
}

// round 5
// speedup vs baseline: 1.1983x; 1.1983x over previous
#include <cuda_runtime.h>
#include <math.h>

#define NB 32
#define NA 5
#define NC 20
#define NH 64
#define NW 64
#define NT 50
#define HW (NH*NW)                  // 4096
#define CELLS_PER_B (NA*HW)         // 20480
#define NCELL (NB*CELLS_PER_B)      // 655360
#define NCH (5+NC)                  // 25
#define TPB 256
#define CPT 4                       // cells per thread
#define CPB (TPB*CPT)               // 1024 cells per block
#define NBLK (NCELL/CPB)            // 640

__device__ float  g_part[NBLK];
__device__ int    g_ticket = 0;

__device__ __forceinline__ float fast_sigmoid(float v) {
    return __fdividef(1.0f, 1.0f + __expf(-v));
}

__global__ void __launch_bounds__(TPB, 6) k_all(const float* __restrict__ out,
                                                const float* __restrict__ target,
                                                const float* __restrict__ anchors,
                                                float* __restrict__ res) {
    __shared__ float4 s_box[NT];
    __shared__ float  s_thr[NT];
    __shared__ int    s_cellt[NT];     // by original t, -1 if invalid
    __shared__ int    s_slot[NT];
    __shared__ int    s_cnt, s_nfix;
    // fix list (targets whose matched cell lies in this block)
    __shared__ int    s_fcell[NT];
    __shared__ float4 s_fbox[NT];
    __shared__ float  s_fga[NT], s_ftx[NT], s_fty[NT], s_ftw[NT], s_fth[NT];
    __shared__ int    s_ftcls[NT];
    __shared__ float  s_ws[TPB/32];
    __shared__ bool   s_last;

    int tid = threadIdx.x;
    int gid0 = blockIdx.x * CPB + tid * CPT;
    int bstart = blockIdx.x * CPB;
    int b = bstart / CELLS_PER_B;      // block fully inside one batch
    int within = gid0 - b * CELLS_PER_B;
    int a = within >> 12;
    int ji = within & 4095;
    int j = ji >> 6, i0 = ji & 63;

    // ---------------- inline per-batch target prep ----------------
    float gx=0, gy=0, gw=0, gh=0, cls=0;
    bool v = false;
    if (tid < NT) {
        const float* tg = target + (size_t)(b*NT + tid)*5;
        cls = tg[0];
        float xn = tg[1], yn = tg[2], wn = tg[3], hn = tg[4];
        v = (xn > 0.0f);
        gx = xn * (float)NW; gy = yn * (float)NH;
        gw = wn * (float)NW; gh = hn * (float)NH;
        s_slot[tid] = v ? 1 : 0;
    }
    if (tid == 0) s_nfix = 0;
    __syncthreads();
    if (tid == 0) {
        int c = 0;
        #pragma unroll
        for (int q = 0; q < NT; q++) { int f = s_slot[q]; s_slot[q] = c; c += f; }
        s_cnt = c;
    }
    __syncthreads();

    int mycell = -1;
    float baw = 0.0f, bah = 0.0f;
    int gi = 0, gj = 0;
    float area = 0.0f;
    float4 mybox;
    if (v) {
        int slot = s_slot[tid];
        mybox = make_float4(gx - 0.5f*gw, gy - 0.5f*gh,
                            gx + 0.5f*gw, gy + 0.5f*gh);
        area = gw * gh;
        s_box[slot] = mybox;
        s_thr[slot] = 0.375f * area;
        // best anchor (first max wins)
        float bi = -1.0f;
        #pragma unroll
        for (int q = 0; q < NA; q++) {
            float aw_ = anchors[2*q], ah_ = anchors[2*q+1];
            float inter = fminf(gw, aw_) * fminf(gh, ah_);
            float uni = fmaxf(area + aw_*ah_ - inter, 1e-10f);
            float iou = inter / uni;
            if (iou > bi) { bi = iou; baw = aw_; bah = ah_;
                mycell = q; }   // reuse mycell as best-anchor temporarily
        }
        int best = mycell;
        gi = min(max((int)floorf(gx), 0), NW-1);
        gj = min(max((int)floorf(gy), 0), NH-1);
        mycell = ((b*NA + best)*NH + gj)*NW + gi;
        s_cellt[tid] = mycell;
    } else if (tid < NT) {
        s_cellt[tid] = -1;
    }
    __syncthreads();
    if (v) {
        bool lw = true;                      // last-writer-wins
        for (int u = tid + 1; u < NT; u++)
            if (s_cellt[u] == mycell) lw = false;
        if (lw && mycell >= bstart && mycell < bstart + CPB) {
            int f = atomicAdd(&s_nfix, 1);
            s_fcell[f] = mycell;
            s_fbox[f]  = mybox;
            s_fga[f]   = area;
            s_ftx[f]   = gx - (float)gi;
            s_fty[f]   = gy - (float)gj;
            s_ftw[f]   = logf(fmaxf(gw, 1e-10f) / baw);
            s_fth[f]   = logf(fmaxf(gh, 1e-10f) / bah);
            s_ftcls[f] = (int)cls;
        }
    }
    __syncthreads();
    int cnt = s_cnt;
    int nfix = s_nfix;

    // ---------------- hot path: 4 cells per thread ----------------
    int base = (b*(NA*NCH) + a*NCH)*HW + ji;
    float4 v0 = *(const float4*)(out + base);
    float4 v1 = *(const float4*)(out + base +   HW);
    float4 v2 = *(const float4*)(out + base + 2*HW);
    float4 v3 = *(const float4*)(out + base + 3*HW);
    float4 v4 = *(const float4*)(out + base + 4*HW);

    float aw = anchors[2*a], ah = anchors[2*a+1];
    float pl[CPT], pr[CPT], pt[CPT], pb[CPT], pthr[CPT], confsq[CPT];
    float acc = 0.0f;
    {
        float o0a[CPT] = {v0.x, v0.y, v0.z, v0.w};
        float o1a[CPT] = {v1.x, v1.y, v1.z, v1.w};
        float o2a[CPT] = {v2.x, v2.y, v2.z, v2.w};
        float o3a[CPT] = {v3.x, v3.y, v3.z, v3.w};
        float o4a[CPT] = {v4.x, v4.y, v4.z, v4.w};
        #pragma unroll
        for (int c = 0; c < CPT; c++) {
            float x = fast_sigmoid(o0a[c]);
            float y = fast_sigmoid(o1a[c]);
            float cf = fast_sigmoid(o4a[c]);
            float pw = __expf(o2a[c]) * aw;
            float ph = __expf(o3a[c]) * ah;
            float px = x + (float)(i0 + c);
            float py = y + (float)j;
            pl[c] = px - 0.5f*pw;  pr[c] = px + 0.5f*pw;
            pt[c] = py - 0.5f*ph;  pb[c] = py + 0.5f*ph;
            pthr[c] = 0.375f * (pw * ph);
            confsq[c] = 0.5f * cf * cf;
            float dx = x - 0.5f, dy = y - 0.5f;
            acc += 0.5f*(dx*dx + dy*dy + o2a[c]*o2a[c] + o3a[c]*o3a[c]);
        }
    }

    bool sil[CPT] = {false, false, false, false};
    #pragma unroll 2
    for (int t = 0; t < cnt; t++) {
        float4 g = s_box[t];
        float thr = s_thr[t];
        #pragma unroll
        for (int c = 0; c < CPT; c++) {
            float l  = fmaxf(pl[c], g.x);
            float tt = fmaxf(pt[c], g.y);
            float r  = fminf(pr[c], g.z);
            float bb = fminf(pb[c], g.w);
            float inter = fmaxf(r - l, 0.0f) * fmaxf(bb - tt, 0.0f);
            sil[c] = sil[c] | (inter > pthr[c] + thr);
        }
    }
    #pragma unroll
    for (int c = 0; c < CPT; c++)
        acc += sil[c] ? 0.0f : confsq[c];

    // ---------------- rare path: matched-cell correction ----------------
    for (int f = 0; f < nfix; f++) {
        int d = s_fcell[f] - gid0;
        if (d >= 0 && d < CPT) {
            float o0 = out[base + d];
            float o1 = out[base + d +   HW];
            float o2 = out[base + d + 2*HW];
            float o3 = out[base + d + 3*HW];
            float o4 = out[base + d + 4*HW];
            float x = fast_sigmoid(o0);
            float y = fast_sigmoid(o1);
            float conf = fast_sigmoid(o4);
            float pw = __expf(o2) * aw;
            float ph = __expf(o3) * ah;
            float parea = pw * ph;
            // default contribution already in acc for this cell
            float ddx = x - 0.5f, ddy = y - 0.5f;
            float D = 0.5f*(ddx*ddx + ddy*ddy + o2*o2 + o3*o3)
                    + (sil[d] ? 0.0f : 0.5f*conf*conf);
            // true contribution
            float4 g = s_fbox[f];
            float l  = fmaxf(pl[d], g.x);
            float tt = fmaxf(pt[d], g.y);
            float rr = fminf(pr[d], g.z);
            float bb = fminf(pb[d], g.w);
            float inter = fmaxf(rr - l, 0.0f) * fmaxf(bb - tt, 0.0f);
            float uni = fmaxf(parea + s_fga[f] - inter, 1e-10f);
            float tconf = __fdividef(inter, uni);
            // class NLL, two passes (no register array)
            int cbase = base + d + 5*HW;
            float m = -1e30f;
            #pragma unroll
            for (int q = 0; q < NC; q++)
                m = fmaxf(m, out[cbase + q*HW]);
            float sum = 0.0f;
            #pragma unroll
            for (int q = 0; q < NC; q++)
                sum += __expf(out[cbase + q*HW] - m);
            float lcls = m + logf(sum) - out[cbase + s_ftcls[f]*HW];
            float dx = x - s_ftx[f], dy = y - s_fty[f];
            float dw = o2 - s_ftw[f], dh = o3 - s_fth[f];
            float dc = conf - tconf;
            acc += 0.5f*(dx*dx + dy*dy + dw*dw + dh*dh + 5.0f*(dc*dc))
                 + lcls - D;
        }
    }

    // ---------------- reduction ----------------
    float vv = acc;
    #pragma unroll
    for (int o = 16; o > 0; o >>= 1)
        vv += __shfl_down_sync(0xffffffffu, vv, o);
    int lane = tid & 31, w = tid >> 5;
    if (lane == 0) s_ws[w] = vv;
    __syncthreads();
    if (w == 0) {
        vv = (lane < TPB/32) ? s_ws[lane] : 0.0f;
        #pragma unroll
        for (int o = 4; o > 0; o >>= 1)
            vv += __shfl_down_sync(0xffffffffu, vv, o);
        if (lane == 0) g_part[blockIdx.x] = vv;
    }

    // arrival ticket: last block sums the 640 partials in double
    __threadfence();
    __syncthreads();
    if (tid == 0) {
        int old = atomicAdd(&g_ticket, 1);
        s_last = (old == NBLK - 1);
    }
    __syncthreads();
    if (s_last) {
        double dacc = 0.0;
        for (int idx = tid; idx < NBLK; idx += TPB) dacc += (double)g_part[idx];
        #pragma unroll
        for (int o = 16; o > 0; o >>= 1)
            dacc += __shfl_down_sync(0xffffffffu, dacc, o);
        __shared__ double s_dw[TPB/32];
        if (lane == 0) s_dw[w] = dacc;
        __syncthreads();
        if (w == 0) {
            dacc = (lane < TPB/32) ? s_dw[lane] : 0.0;
            #pragma unroll
            for (int o = 4; o > 0; o >>= 1)
                dacc += __shfl_down_sync(0xffffffffu, dacc, o);
            if (lane == 0) { res[0] = (float)dacc; g_ticket = 0; }
        }
    }
}

extern "C" void kernel_launch(void* const* d_in, const int* in_sizes, int n_in,
                              void* d_out, int out_size) {
    const float* output  = (const float*)d_in[0];
    const float* target  = (const float*)d_in[1];
    const float* anchors = (const float*)d_in[2];
    float* res = (float*)d_out;
    (void)in_sizes; (void)n_in; (void)out_size;

    k_all<<<NBLK, TPB>>>(output, target, anchors, res);
}